// round 11
// baseline (speedup 1.0000x reference)
#include <cuda_runtime.h>
#include <cuda_fp16.h>
#include <stdint.h>
#include <math.h>

#define NPV   32768          // nodes in perturbed graph
#define NNV   128            // nodes in non-perturbed graph
#define EPV   524288         // edges p
#define ENV   2048           // edges np
#define CH    128            // channels
#define WALKN 7
#define BATN  256
#define TOTP  (EPV + NPV)    // CSR entries p (edges + self loops)
#define TOTN  (ENV + NNV)
#define CC    (CH * CH)

// ---------------- device scratch (static, no allocation) ----------------
// Zero at load; every buffer that must be zero at run start is re-zeroed by
// the kernel that consumes it (or by k_epi), so each replay is identical.
static __device__ int    g_deg_p[NPV];
static __device__ int    g_deg_n[NNV];
static __device__ float  g_dinv_p[NPV];
static __device__ float  g_dinv_n[NNV];
static __device__ int    g_rs_p[NPV + 1];
static __device__ int    g_rs_n[NNV + 1];
static __device__ int    g_cur_p[NPV];
static __device__ int    g_cur_n[NNV];
static __device__ int    g_post[32];             // window prefix publish: val+1, 0 = empty
static __device__ int2   g_colw_p[TOTP];         // {src, float_bits(norm)}
static __device__ int2   g_colw_n[TOTN];
static __device__ __half g_h [2][NPV * CH];      // ping-pong g = A^t x_p (fp16 state)
static __device__ __half g_hn[2][NNV * CH];
static __device__ float  g_c[2][NPV];            // ping-pong c = A^t 1 (fp32)
static __device__ float  g_cn[2][NNV];
static __device__ float  g_PT[(WALKN + 1) * CC]; // (W^t)^T (fp32)
static __device__ float  g_Bv[(WALKN + 1) * CH]; // b^T W^t
static __device__ float  g_ptr[WALKN * BATN];    // block traces of g_t W^t
static __device__ float  g_ntr[WALKN];
static __device__ float  g_q [WALKN * BATN];     // q'_a = <c_a block, B_a>
static __device__ float  g_qn[WALKN];
static __device__ int    g_bnz;                  // any(b != 0)? plain store each run

__device__ __forceinline__ int eget(const void* p, int is64, int i) {
    return is64 ? (int)((const long long*)p)[i] : ((const int*)p)[i];
}

// Block-local int64/int32 detection over this block's own 256-element window:
// in int64 layout the odd 32-bit words are high halves of values < 2^31 -> 0.
__device__ __forceinline__ int detect64(const int* w, int base, int t) {
    int nz = w[2 * (base + t) + 1] != 0;
    return !__syncthreads_or(nz);
}

// ---------------- k_deg: local detect + degree count + x -> fp16 conversion --
__global__ void k_deg(const void* __restrict__ eip, const void* __restrict__ ein,
                      const float* __restrict__ xp, const float* __restrict__ xnp) {
    int bid = blockIdx.x, t = threadIdx.x;
    if (bid < 2048) {
        int base = bid * 256;
        int is64 = detect64((const int*)eip, base, t);
        int d = eget(eip, is64, EPV + base + t);
        atomicAdd(&g_deg_p[d], 1);
    } else if (bid < 2056) {
        int base = (bid - 2048) * 256;
        int is64 = detect64((const int*)ein, base, t);
        int d = eget(ein, is64, ENV + base + t);
        atomicAdd(&g_deg_n[d], 1);
    } else if (bid < 4104) {
        int tix = (bid - 2056) * 256 + t;            // 8 floats per thread
        const float4* x4 = (const float4*)xp;
        float4 a = x4[tix * 2], b = x4[tix * 2 + 1];
        __half2 h0 = __floats2half2_rn(a.x, a.y), h1 = __floats2half2_rn(a.z, a.w);
        __half2 h2 = __floats2half2_rn(b.x, b.y), h3 = __floats2half2_rn(b.z, b.w);
        uint4 st;
        *reinterpret_cast<__half2*>(&st.x) = h0;
        *reinterpret_cast<__half2*>(&st.y) = h1;
        *reinterpret_cast<__half2*>(&st.z) = h2;
        *reinterpret_cast<__half2*>(&st.w) = h3;
        reinterpret_cast<uint4*>(&g_h[0][0])[tix] = st;
    } else {
        int tix = (bid - 4104) * 256 + t;
        const float4* x4 = (const float4*)xnp;
        float4 a = x4[tix * 2], b = x4[tix * 2 + 1];
        __half2 h0 = __floats2half2_rn(a.x, a.y), h1 = __floats2half2_rn(a.z, a.w);
        __half2 h2 = __floats2half2_rn(b.x, b.y), h3 = __floats2half2_rn(b.z, b.w);
        uint4 st;
        *reinterpret_cast<__half2*>(&st.x) = h0;
        *reinterpret_cast<__half2*>(&st.y) = h1;
        *reinterpret_cast<__half2*>(&st.z) = h2;
        *reinterpret_cast<__half2*>(&st.w) = h3;
        reinterpret_cast<uint4*>(&g_hn[0][0])[tix] = st;
    }
}

// ---------------- fused scan (p windows w/ publish-poll, np, W powers, c) ----
__global__ void __launch_bounds__(1024) k_scanfuse(const float* __restrict__ W,
                                                   const float* __restrict__ bg) {
    int bid = blockIdx.x, t = threadIdx.x, lane = t & 31, w = t >> 5;
    if (bid < 32) {
        __shared__ int ws[32];
        __shared__ int s_off;
        int i = bid * 1024 + t;
        int L = g_deg_p[i] + 1;                // + self loop
        g_deg_p[i] = 0;                        // restore load-time state
        g_dinv_p[i] = rsqrtf((float)L);
        int s = L;
        for (int o = 1; o < 32; o <<= 1) {
            int u = __shfl_up_sync(0xffffffffu, s, o);
            if (lane >= o) s += u;
        }
        if (lane == 31) ws[w] = s;
        __syncthreads();
        if (w == 0) {
            int v = ws[lane], ss = v;
            for (int o = 1; o < 32; o <<= 1) {
                int u = __shfl_up_sync(0xffffffffu, ss, o);
                if (lane >= o) ss += u;
            }
            ws[lane] = ss - v;                 // exclusive warp offsets
        }
        __syncthreads();
        int ex = s - L + ws[w];                // window-local exclusive
        if (t == 1023) atomicExch(&g_post[bid], (ex + L) + 1);   // publish total
        if (w == 0) {
            int pv = 0;
            if (lane < bid) {
                int v;
                do { v = atomicAdd(&g_post[lane], 0); } while (v == 0);
                pv = v - 1;
            }
            pv += __shfl_xor_sync(0xffffffffu, pv, 16);
            pv += __shfl_xor_sync(0xffffffffu, pv, 8);
            pv += __shfl_xor_sync(0xffffffffu, pv, 4);
            pv += __shfl_xor_sync(0xffffffffu, pv, 2);
            pv += __shfl_xor_sync(0xffffffffu, pv, 1);
            if (lane == 0) s_off = pv;
        }
        __syncthreads();
        int v = ex + s_off;
        g_rs_p[i] = v;
        g_cur_p[i] = v;
        if (bid == 31 && t == 1023) g_rs_p[NPV] = TOTP;
    } else if (bid == 32) {
        __shared__ int ws[4];
        int valid = t < NNV;
        int L = 1;
        if (valid) {
            L = g_deg_n[t] + 1;
            g_deg_n[t] = 0;
            g_dinv_n[t] = rsqrtf((float)L);
        }
        int s = L;
        for (int o = 1; o < 32; o <<= 1) {
            int u = __shfl_up_sync(0xffffffffu, s, o);
            if (lane >= o) s += u;
        }
        if (lane == 31 && w < 4) ws[w] = s;
        __syncthreads();
        if (valid) {
            int off = 0;
            for (int k = 0; k < 4; k++) off += (k < w) ? ws[k] : 0;
            int ex = s - L + off;
            g_rs_n[t] = ex;
            g_cur_n[t] = ex;
        }
        if (t == 0) g_rs_n[NNV] = TOTN;
    } else {
        __shared__ float prev[8][CH];
        __shared__ int s_nz;
        int rl = t >> 7, c = t & 127;
        int rr = (bid - 33) * 8 + rl;
        int valid = rr <= CH;
        int cid = (bid - 33) * 1024 + t;
        for (int i2 = cid; i2 < NPV; i2 += 17 * 1024) g_c[0][i2] = 1.0f;
        if (cid < NNV) g_cn[0][cid] = 1.0f;

        float pv = 0.0f;
        if (valid) pv = (rr < CH) ? ((c == rr) ? 1.0f : 0.0f) : bg[c];
        if (t == 0) s_nz = 0;
        prev[rl][c] = pv;
        __syncthreads();
        if (valid && rr == CH && pv != 0.0f) atomicOr(&s_nz, 1);
        __syncthreads();
        if (valid && rr == CH && c == 0) g_bnz = s_nz;
        for (int tt = 1; tt <= WALKN; tt++) {
            float acc = 0.0f;
#pragma unroll 16
            for (int m = 0; m < CH; m++) acc = fmaf(prev[rl][m], W[m * CH + c], acc);
            __syncthreads();
            prev[rl][c] = acc;
            if (valid) {
                if (rr < CH) g_PT[tt * CC + c * CH + rr] = acc;  // transposed
                else         g_Bv[tt * CH + c] = acc;
            }
            __syncthreads();
        }
    }
}

// ---------------- CSR fill (edges + self loops, with norms; local detect) ---
__global__ void k_fill(const void* __restrict__ eip, const void* __restrict__ ein) {
    int bid = blockIdx.x, t = threadIdx.x;
    if (bid < 2048) {
        int base = bid * 256;
        int is64 = detect64((const int*)eip, base, t);
        int s = eget(eip, is64, base + t);
        int d = eget(eip, is64, EPV + base + t);
        float w = g_dinv_p[s] * g_dinv_p[d];
        int pos = atomicAdd(&g_cur_p[d], 1);
        g_colw_p[pos] = make_int2(s, __float_as_int(w));
    } else if (bid < 2176) {
        int n = (bid - 2048) * 256 + t;
        float di = g_dinv_p[n];
        int pos = atomicAdd(&g_cur_p[n], 1);
        g_colw_p[pos] = make_int2(n, __float_as_int(di * di));
    } else if (bid < 2184) {
        int base = (bid - 2176) * 256;
        int is64 = detect64((const int*)ein, base, t);
        int s = eget(ein, is64, base + t);
        int d = eget(ein, is64, ENV + base + t);
        float w = g_dinv_n[s] * g_dinv_n[d];
        int pos = atomicAdd(&g_cur_n[d], 1);
        g_colw_n[pos] = make_int2(s, __float_as_int(w));
    } else if (t < NNV) {
        float di = g_dinv_n[t];
        int pos = atomicAdd(&g_cur_n[t], 1);
        g_colw_n[pos] = make_int2(t, __float_as_int(di * di));
    }
}

// ---------------- main per-step kernel ----------------
// fp16 gather, fp32 accumulate. CSR metadata for the row is loaded ONCE per
// 32-edge chunk (one coalesced int2 per lane) and distributed via shuffles,
// removing the per-edge CSR load AND its dependency chain; gathers issue
// 4-deep for MLP.
#define EDGE_BODY(ARR, SJ, WJ)                                              \
    {   uint2 v = ARR[(SJ) * 32 + lane];                                    \
        float2 fa = __half22float2(*reinterpret_cast<__half2*>(&v.x));      \
        float2 fb = __half22float2(*reinterpret_cast<__half2*>(&v.y));      \
        ax = fmaf(WJ, fa.x, ax); ay = fmaf(WJ, fa.y, ay);                   \
        az = fmaf(WJ, fb.x, az); aw = fmaf(WJ, fb.y, aw); }

__global__ void __launch_bounds__(256) k_agg(int a, int last) {
    int gw   = blockIdx.x * 8 + (threadIdx.x >> 5);   // warp per dst row
    int lane = threadIdx.x & 31;
    int pa = (a - 1) & 1, ca = a & 1;
    int cpath = g_bnz && !last;                       // b==0 fast path (uniform)

    if (gw < NPV) {
        const uint2* gin = (const uint2*)&g_h[pa][0];
        const float* cin = g_c[pa];
        int s0 = g_rs_p[gw], s1 = g_rs_p[gw + 1];
        float ax = 0.f, ay = 0.f, az = 0.f, aw = 0.f, cacc = 0.f;
        for (int base = s0; base < s1; base += 32) {
            int rem = s1 - base; if (rem > 32) rem = 32;
            int2 cw = g_colw_p[base + (lane < rem ? lane : rem - 1)];
            int j = 0;
            for (; j + 4 <= rem; j += 4) {
                int s_0 = __shfl_sync(0xffffffffu, cw.x, j);
                int s_1 = __shfl_sync(0xffffffffu, cw.x, j + 1);
                int s_2 = __shfl_sync(0xffffffffu, cw.x, j + 2);
                int s_3 = __shfl_sync(0xffffffffu, cw.x, j + 3);
                float w_0 = __int_as_float(__shfl_sync(0xffffffffu, cw.y, j));
                float w_1 = __int_as_float(__shfl_sync(0xffffffffu, cw.y, j + 1));
                float w_2 = __int_as_float(__shfl_sync(0xffffffffu, cw.y, j + 2));
                float w_3 = __int_as_float(__shfl_sync(0xffffffffu, cw.y, j + 3));
                uint2 v0 = gin[s_0 * 32 + lane];
                uint2 v1 = gin[s_1 * 32 + lane];
                uint2 v2 = gin[s_2 * 32 + lane];
                uint2 v3 = gin[s_3 * 32 + lane];
                float2 f;
                f = __half22float2(*reinterpret_cast<__half2*>(&v0.x));
                ax = fmaf(w_0, f.x, ax); ay = fmaf(w_0, f.y, ay);
                f = __half22float2(*reinterpret_cast<__half2*>(&v0.y));
                az = fmaf(w_0, f.x, az); aw = fmaf(w_0, f.y, aw);
                f = __half22float2(*reinterpret_cast<__half2*>(&v1.x));
                ax = fmaf(w_1, f.x, ax); ay = fmaf(w_1, f.y, ay);
                f = __half22float2(*reinterpret_cast<__half2*>(&v1.y));
                az = fmaf(w_1, f.x, az); aw = fmaf(w_1, f.y, aw);
                f = __half22float2(*reinterpret_cast<__half2*>(&v2.x));
                ax = fmaf(w_2, f.x, ax); ay = fmaf(w_2, f.y, ay);
                f = __half22float2(*reinterpret_cast<__half2*>(&v2.y));
                az = fmaf(w_2, f.x, az); aw = fmaf(w_2, f.y, aw);
                f = __half22float2(*reinterpret_cast<__half2*>(&v3.x));
                ax = fmaf(w_3, f.x, ax); ay = fmaf(w_3, f.y, ay);
                f = __half22float2(*reinterpret_cast<__half2*>(&v3.y));
                az = fmaf(w_3, f.x, az); aw = fmaf(w_3, f.y, aw);
                if (cpath && lane == 0)
                    cacc += w_0 * cin[s_0] + w_1 * cin[s_1]
                          + w_2 * cin[s_2] + w_3 * cin[s_3];
            }
            for (; j < rem; j++) {
                int   sj = __shfl_sync(0xffffffffu, cw.x, j);
                float wj = __int_as_float(__shfl_sync(0xffffffffu, cw.y, j));
                EDGE_BODY(gin, sj, wj)
                if (cpath && lane == 0) cacc += wj * cin[sj];
            }
        }
        if (!last) {                                  // g_WALKN never consumed
            __half2 o0 = __floats2half2_rn(ax, ay);
            __half2 o1 = __floats2half2_rn(az, aw);
            uint2 st;
            *reinterpret_cast<__half2*>(&st.x) = o0;
            *reinterpret_cast<__half2*>(&st.y) = o1;
            reinterpret_cast<uint2*>(&g_h[ca][0])[gw * 32 + lane] = st;
        }
        // fused block trace from fp32 accumulators: g[r,:] . W^a[:, r&127]
        int k = gw & 127, bb = gw >> 7;
        float4 wt = ((const float4*)(g_PT + a * CC + k * CH))[lane];
        float part = ax * wt.x + ay * wt.y + az * wt.z + aw * wt.w;
        part += __shfl_xor_sync(0xffffffffu, part, 16);
        part += __shfl_xor_sync(0xffffffffu, part, 8);
        part += __shfl_xor_sync(0xffffffffu, part, 4);
        part += __shfl_xor_sync(0xffffffffu, part, 2);
        part += __shfl_xor_sync(0xffffffffu, part, 1);
        if (lane == 0) {
            atomicAdd(&g_ptr[(a - 1) * BATN + bb], part);
            if (cpath) {
                g_c[ca][gw] = cacc;
                atomicAdd(&g_q[(a - 1) * BATN + bb], cacc * g_Bv[a * CH + k]);
            }
        }
    } else {
        int w2 = gw - NPV;                            // np graph, 128 dst rows
        const uint2* gin = (const uint2*)&g_hn[pa][0];
        const float* cin = g_cn[pa];
        int s0 = g_rs_n[w2], s1 = g_rs_n[w2 + 1];
        float ax = 0.f, ay = 0.f, az = 0.f, aw = 0.f, cacc = 0.f;
        for (int base = s0; base < s1; base += 32) {
            int rem = s1 - base; if (rem > 32) rem = 32;
            int2 cw = g_colw_n[base + (lane < rem ? lane : rem - 1)];
            for (int j = 0; j < rem; j++) {
                int   sj = __shfl_sync(0xffffffffu, cw.x, j);
                float wj = __int_as_float(__shfl_sync(0xffffffffu, cw.y, j));
                EDGE_BODY(gin, sj, wj)
                if (cpath && lane == 0) cacc += wj * cin[sj];
            }
        }
        if (!last) {
            __half2 o0 = __floats2half2_rn(ax, ay);
            __half2 o1 = __floats2half2_rn(az, aw);
            uint2 st;
            *reinterpret_cast<__half2*>(&st.x) = o0;
            *reinterpret_cast<__half2*>(&st.y) = o1;
            reinterpret_cast<uint2*>(&g_hn[ca][0])[w2 * 32 + lane] = st;
        }
        float4 wt = ((const float4*)(g_PT + a * CC + w2 * CH))[lane];
        float part = ax * wt.x + ay * wt.y + az * wt.z + aw * wt.w;
        part += __shfl_xor_sync(0xffffffffu, part, 16);
        part += __shfl_xor_sync(0xffffffffu, part, 8);
        part += __shfl_xor_sync(0xffffffffu, part, 4);
        part += __shfl_xor_sync(0xffffffffu, part, 2);
        part += __shfl_xor_sync(0xffffffffu, part, 1);
        if (lane == 0) {
            atomicAdd(&g_ntr[a - 1], part);
            if (cpath) {
                g_cn[ca][w2] = cacc;
                atomicAdd(&g_qn[a - 1], cacc * g_Bv[a * CH + w2]);
            }
        }
    }
}

// ---------------- epilogue: bias corr, standardize, MLP, sigmoid, reset -----
__device__ __forceinline__ float blk_sum(float v, float* sm) {
    int t = threadIdx.x, lane = t & 31, w = t >> 5;
    v += __shfl_xor_sync(0xffffffffu, v, 16);
    v += __shfl_xor_sync(0xffffffffu, v, 8);
    v += __shfl_xor_sync(0xffffffffu, v, 4);
    v += __shfl_xor_sync(0xffffffffu, v, 2);
    v += __shfl_xor_sync(0xffffffffu, v, 1);
    if (lane == 0) sm[w] = v;
    __syncthreads();
    if (w == 0) {
        float r = (lane < 8) ? sm[lane] : 0.0f;
        r += __shfl_xor_sync(0xffffffffu, r, 4);
        r += __shfl_xor_sync(0xffffffffu, r, 2);
        r += __shfl_xor_sync(0xffffffffu, r, 1);
        if (lane == 0) sm[8] = r;
    }
    __syncthreads();
    float out = sm[8];
    __syncthreads();
    return out;
}

__global__ void k_epi(const float* __restrict__ y,  const float* __restrict__ bg,
                      const float* __restrict__ W1, const float* __restrict__ b1,
                      const float* __restrict__ W2, const float* __restrict__ b2,
                      float* __restrict__ out) {
    __shared__ float sm[9];
    int b = threadIdx.x;
    float sumb = 0.f;
    for (int k = 0; k < CH; k++) sumb += bg[k];
    float ysc = (y[b] - 0.5f) * 2.0f;

    float v[WALKN];
    float cp = 0.f, cn = 0.f;
    for (int s = 0; s < WALKN; s++) {
        float qp = (s == 0) ? sumb : g_q[(s - 1) * BATN + b];
        float qn = (s == 0) ? sumb : g_qn[s - 1];
        cp += qp; cn += qn;
        float pv = g_ptr[s * BATN + b] + cp;
        float nv = g_ntr[s] + cn;
        v[s] = (pv - nv) * ysc;
    }
    for (int s = 0; s < WALKN; s++) {
        float mu = blk_sum(v[s], sm) * (1.0f / BATN);
        float d = v[s] - mu;
        float var = blk_sum(d * d, sm) * (1.0f / (BATN - 1));
        v[s] = d / sqrtf(var);
    }
    float o2 = b2[0];
    for (int j = 0; j < 15; j++) {
        float h = b1[j];
        for (int s = 0; s < WALKN; s++) h = fmaf(v[s], W1[s * 15 + j], h);
        h = fmaxf(h, 0.0f);
        o2 = fmaf(h, W2[j], o2);
    }
    out[b] = 1.0f / (1.0f + expf(-o2));

    // restore load-time state for the next identical replay
    __syncthreads();
    for (int s = 0; s < WALKN; s++) { g_ptr[s * BATN + b] = 0.0f; g_q[s * BATN + b] = 0.0f; }
    if (b < WALKN) { g_ntr[b] = 0.0f; g_qn[b] = 0.0f; }
    if (b < 32)    g_post[b] = 0;
}

// ---------------- launch ----------------
extern "C" void kernel_launch(void* const* d_in, const int* in_sizes, int n_in,
                              void* d_out, int out_size) {
    const float* x_p  = (const float*)d_in[0];
    const float* x_np = (const float*)d_in[1];
    const float* y    = (const float*)d_in[2];
    const void*  eip  = d_in[3];
    const void*  ein  = d_in[4];
    const float* W    = (const float*)d_in[5];
    const float* bg   = (const float*)d_in[6];
    const float* W1   = (const float*)d_in[7];
    const float* b1   = (const float*)d_in[8];
    const float* W2   = (const float*)d_in[9];
    const float* b2   = (const float*)d_in[10];
    float* out = (float*)d_out;

    k_deg<<<4112, 256>>>(eip, ein, x_p, x_np);
    k_scanfuse<<<50, 1024>>>(W, bg);
    k_fill<<<2185, 256>>>(eip, ein);
    for (int a = 1; a <= WALKN; a++)
        k_agg<<<(NPV + NNV) / 8, 256>>>(a, a == WALKN);
    k_epi<<<1, BATN>>>(y, bg, W1, b1, W2, b2, out);
    (void)in_sizes; (void)n_in; (void)out_size;
}

// round 12
// speedup vs baseline: 1.0426x; 1.0426x over previous
#include <cuda_runtime.h>
#include <cuda_fp16.h>
#include <stdint.h>
#include <math.h>

#define NPV   32768          // nodes in perturbed graph
#define NNV   128            // nodes in non-perturbed graph
#define EPV   524288         // edges p
#define ENV   2048           // edges np
#define CH    128            // channels
#define WALKN 7
#define BATN  256
#define TOTP  (EPV + NPV)    // CSR entries p (edges + self loops)
#define TOTN  (ENV + NNV)
#define CC    (CH * CH)

// ---------------- device scratch (static, no allocation) ----------------
// Zero at load; every buffer that must be zero at run start is re-zeroed by
// the kernel that consumes it (or by k_epi), so each replay is identical.
static __device__ int    g_deg_p[NPV];
static __device__ int    g_deg_n[NNV];
static __device__ float  g_dinv_p[NPV];
static __device__ float  g_dinv_n[NNV];
static __device__ int    g_rs_p[NPV + 1];
static __device__ int    g_rs_n[NNV + 1];
static __device__ int    g_cur_p[NPV];
static __device__ int    g_cur_n[NNV];
static __device__ int    g_post[32];             // window prefix publish: val+1, 0 = empty
static __device__ int2   g_colw_p[TOTP];         // {src, float_bits(norm)}
static __device__ int2   g_colw_n[TOTN];
static __device__ __half g_h [2][NPV * CH];      // ping-pong g = A^t x_p (fp16 state)
static __device__ __half g_hn[2][NNV * CH];
static __device__ float  g_c[2][NPV];            // ping-pong c = A^t 1 (fp32)
static __device__ float  g_cn[2][NNV];
static __device__ float  g_PT[(WALKN + 1) * CC]; // (W^t)^T (fp32)
static __device__ float  g_Bv[(WALKN + 1) * CH]; // b^T W^t
static __device__ float  g_ptr[WALKN * BATN];    // block traces of g_t W^t
static __device__ float  g_ntr[WALKN];
static __device__ float  g_q [WALKN * BATN];     // q'_a = <c_a block, B_a>
static __device__ float  g_qn[WALKN];
static __device__ int    g_bnz;                  // any(b != 0)? plain store each run

__device__ __forceinline__ int eget(const void* p, int is64, int i) {
    return is64 ? (int)((const long long*)p)[i] : ((const int*)p)[i];
}

// Block-local int64/int32 detection over this block's own 256-element window:
// in int64 layout the odd 32-bit words are high halves of values < 2^31 -> 0.
__device__ __forceinline__ int detect64(const int* w, int base, int t) {
    int nz = w[2 * (base + t) + 1] != 0;
    return !__syncthreads_or(nz);
}

// ---------------- k_deg: local detect + degree count + x -> fp16 conversion --
__global__ void k_deg(const void* __restrict__ eip, const void* __restrict__ ein,
                      const float* __restrict__ xp, const float* __restrict__ xnp) {
    int bid = blockIdx.x, t = threadIdx.x;
    if (bid < 2048) {
        int base = bid * 256;
        int is64 = detect64((const int*)eip, base, t);
        int d = eget(eip, is64, EPV + base + t);
        atomicAdd(&g_deg_p[d], 1);
    } else if (bid < 2056) {
        int base = (bid - 2048) * 256;
        int is64 = detect64((const int*)ein, base, t);
        int d = eget(ein, is64, ENV + base + t);
        atomicAdd(&g_deg_n[d], 1);
    } else if (bid < 4104) {
        int tix = (bid - 2056) * 256 + t;            // 8 floats per thread
        const float4* x4 = (const float4*)xp;
        float4 a = x4[tix * 2], b = x4[tix * 2 + 1];
        __half2 h0 = __floats2half2_rn(a.x, a.y), h1 = __floats2half2_rn(a.z, a.w);
        __half2 h2 = __floats2half2_rn(b.x, b.y), h3 = __floats2half2_rn(b.z, b.w);
        uint4 st;
        *reinterpret_cast<__half2*>(&st.x) = h0;
        *reinterpret_cast<__half2*>(&st.y) = h1;
        *reinterpret_cast<__half2*>(&st.z) = h2;
        *reinterpret_cast<__half2*>(&st.w) = h3;
        reinterpret_cast<uint4*>(&g_h[0][0])[tix] = st;
    } else {
        int tix = (bid - 4104) * 256 + t;
        const float4* x4 = (const float4*)xnp;
        float4 a = x4[tix * 2], b = x4[tix * 2 + 1];
        __half2 h0 = __floats2half2_rn(a.x, a.y), h1 = __floats2half2_rn(a.z, a.w);
        __half2 h2 = __floats2half2_rn(b.x, b.y), h3 = __floats2half2_rn(b.z, b.w);
        uint4 st;
        *reinterpret_cast<__half2*>(&st.x) = h0;
        *reinterpret_cast<__half2*>(&st.y) = h1;
        *reinterpret_cast<__half2*>(&st.z) = h2;
        *reinterpret_cast<__half2*>(&st.w) = h3;
        reinterpret_cast<uint4*>(&g_hn[0][0])[tix] = st;
    }
}

// ---------------- fused scan (p windows w/ publish-poll, np, W powers, c) ----
__global__ void __launch_bounds__(1024) k_scanfuse(const float* __restrict__ W,
                                                   const float* __restrict__ bg) {
    int bid = blockIdx.x, t = threadIdx.x, lane = t & 31, w = t >> 5;
    if (bid < 32) {
        __shared__ int ws[32];
        __shared__ int s_off;
        int i = bid * 1024 + t;
        int L = g_deg_p[i] + 1;                // + self loop
        g_deg_p[i] = 0;                        // restore load-time state
        g_dinv_p[i] = rsqrtf((float)L);
        int s = L;
        for (int o = 1; o < 32; o <<= 1) {
            int u = __shfl_up_sync(0xffffffffu, s, o);
            if (lane >= o) s += u;
        }
        if (lane == 31) ws[w] = s;
        __syncthreads();
        if (w == 0) {
            int v = ws[lane], ss = v;
            for (int o = 1; o < 32; o <<= 1) {
                int u = __shfl_up_sync(0xffffffffu, ss, o);
                if (lane >= o) ss += u;
            }
            ws[lane] = ss - v;                 // exclusive warp offsets
        }
        __syncthreads();
        int ex = s - L + ws[w];                // window-local exclusive
        if (t == 1023) atomicExch(&g_post[bid], (ex + L) + 1);   // publish total
        if (w == 0) {
            int pv = 0;
            if (lane < bid) {
                int v;
                do { v = atomicAdd(&g_post[lane], 0); } while (v == 0);
                pv = v - 1;
            }
            pv += __shfl_xor_sync(0xffffffffu, pv, 16);
            pv += __shfl_xor_sync(0xffffffffu, pv, 8);
            pv += __shfl_xor_sync(0xffffffffu, pv, 4);
            pv += __shfl_xor_sync(0xffffffffu, pv, 2);
            pv += __shfl_xor_sync(0xffffffffu, pv, 1);
            if (lane == 0) s_off = pv;
        }
        __syncthreads();
        int v = ex + s_off;
        g_rs_p[i] = v;
        g_cur_p[i] = v;
        if (bid == 31 && t == 1023) g_rs_p[NPV] = TOTP;
    } else if (bid == 32) {
        __shared__ int ws[4];
        int valid = t < NNV;
        int L = 1;
        if (valid) {
            L = g_deg_n[t] + 1;
            g_deg_n[t] = 0;
            g_dinv_n[t] = rsqrtf((float)L);
        }
        int s = L;
        for (int o = 1; o < 32; o <<= 1) {
            int u = __shfl_up_sync(0xffffffffu, s, o);
            if (lane >= o) s += u;
        }
        if (lane == 31 && w < 4) ws[w] = s;
        __syncthreads();
        if (valid) {
            int off = 0;
            for (int k = 0; k < 4; k++) off += (k < w) ? ws[k] : 0;
            int ex = s - L + off;
            g_rs_n[t] = ex;
            g_cur_n[t] = ex;
        }
        if (t == 0) g_rs_n[NNV] = TOTN;
    } else {
        __shared__ float prev[8][CH];
        __shared__ int s_nz;
        int rl = t >> 7, c = t & 127;
        int rr = (bid - 33) * 8 + rl;
        int valid = rr <= CH;
        int cid = (bid - 33) * 1024 + t;
        for (int i2 = cid; i2 < NPV; i2 += 17 * 1024) g_c[0][i2] = 1.0f;
        if (cid < NNV) g_cn[0][cid] = 1.0f;

        float pv = 0.0f;
        if (valid) pv = (rr < CH) ? ((c == rr) ? 1.0f : 0.0f) : bg[c];
        if (t == 0) s_nz = 0;
        prev[rl][c] = pv;
        __syncthreads();
        if (valid && rr == CH && pv != 0.0f) atomicOr(&s_nz, 1);
        __syncthreads();
        if (valid && rr == CH && c == 0) g_bnz = s_nz;
        for (int tt = 1; tt <= WALKN; tt++) {
            float acc = 0.0f;
#pragma unroll 16
            for (int m = 0; m < CH; m++) acc = fmaf(prev[rl][m], W[m * CH + c], acc);
            __syncthreads();
            prev[rl][c] = acc;
            if (valid) {
                if (rr < CH) g_PT[tt * CC + c * CH + rr] = acc;  // transposed
                else         g_Bv[tt * CH + c] = acc;
            }
            __syncthreads();
        }
    }
}

// ---------------- CSR fill (edges + self loops, with norms; local detect) ---
__global__ void k_fill(const void* __restrict__ eip, const void* __restrict__ ein) {
    int bid = blockIdx.x, t = threadIdx.x;
    if (bid < 2048) {
        int base = bid * 256;
        int is64 = detect64((const int*)eip, base, t);
        int s = eget(eip, is64, base + t);
        int d = eget(eip, is64, EPV + base + t);
        float w = g_dinv_p[s] * g_dinv_p[d];
        int pos = atomicAdd(&g_cur_p[d], 1);
        g_colw_p[pos] = make_int2(s, __float_as_int(w));
    } else if (bid < 2176) {
        int n = (bid - 2048) * 256 + t;
        float di = g_dinv_p[n];
        int pos = atomicAdd(&g_cur_p[n], 1);
        g_colw_p[pos] = make_int2(n, __float_as_int(di * di));
    } else if (bid < 2184) {
        int base = (bid - 2176) * 256;
        int is64 = detect64((const int*)ein, base, t);
        int s = eget(ein, is64, base + t);
        int d = eget(ein, is64, ENV + base + t);
        float w = g_dinv_n[s] * g_dinv_n[d];
        int pos = atomicAdd(&g_cur_n[d], 1);
        g_colw_n[pos] = make_int2(s, __float_as_int(w));
    } else if (t < NNV) {
        float di = g_dinv_n[t];
        int pos = atomicAdd(&g_cur_n[t], 1);
        g_colw_n[pos] = make_int2(t, __float_as_int(di * di));
    }
}

// ---------------- main per-step kernel ----------------
// fp16 gather, fp32 accumulate, 4-deep MLP: 4 independent broadcast CSR loads
// (all lanes same address = 1 sector each) issue back-to-back, then 4
// independent row gathers. 8 loads in flight per warp; no shuffle chains.
#define FMA8(V, W_)                                                          \
    {   float2 f;                                                            \
        f = __half22float2(*reinterpret_cast<__half2*>(&(V).x));             \
        ax = fmaf((W_), f.x, ax); ay = fmaf((W_), f.y, ay);                  \
        f = __half22float2(*reinterpret_cast<__half2*>(&(V).y));             \
        az = fmaf((W_), f.x, az); aw = fmaf((W_), f.y, aw); }

__global__ void __launch_bounds__(256) k_agg(int a, int last) {
    int gw   = blockIdx.x * 8 + (threadIdx.x >> 5);   // warp per dst row
    int lane = threadIdx.x & 31;
    int pa = (a - 1) & 1, ca = a & 1;
    int cpath = g_bnz && !last;                       // b==0 fast path (uniform)

    if (gw < NPV) {
        const uint2* gin = (const uint2*)&g_h[pa][0];
        const float* cin = g_c[pa];
        int s0 = g_rs_p[gw], s1 = g_rs_p[gw + 1];
        float ax = 0.f, ay = 0.f, az = 0.f, aw = 0.f, cacc = 0.f;
        int e = s0;
        for (; e + 4 <= s1; e += 4) {
            int2 c0 = g_colw_p[e];
            int2 c1 = g_colw_p[e + 1];
            int2 c2 = g_colw_p[e + 2];
            int2 c3 = g_colw_p[e + 3];
            uint2 v0 = gin[c0.x * 32 + lane];
            uint2 v1 = gin[c1.x * 32 + lane];
            uint2 v2 = gin[c2.x * 32 + lane];
            uint2 v3 = gin[c3.x * 32 + lane];
            float w0 = __int_as_float(c0.y), w1 = __int_as_float(c1.y);
            float w2 = __int_as_float(c2.y), w3 = __int_as_float(c3.y);
            FMA8(v0, w0) FMA8(v1, w1) FMA8(v2, w2) FMA8(v3, w3)
            if (cpath && lane == 0)
                cacc += w0 * cin[c0.x] + w1 * cin[c1.x]
                      + w2 * cin[c2.x] + w3 * cin[c3.x];
        }
        for (; e < s1; e++) {
            int2 c0 = g_colw_p[e];
            uint2 v0 = gin[c0.x * 32 + lane];
            float w0 = __int_as_float(c0.y);
            FMA8(v0, w0)
            if (cpath && lane == 0) cacc += w0 * cin[c0.x];
        }
        if (!last) {                                  // g_WALKN never consumed
            __half2 o0 = __floats2half2_rn(ax, ay);
            __half2 o1 = __floats2half2_rn(az, aw);
            uint2 st;
            *reinterpret_cast<__half2*>(&st.x) = o0;
            *reinterpret_cast<__half2*>(&st.y) = o1;
            reinterpret_cast<uint2*>(&g_h[ca][0])[gw * 32 + lane] = st;
        }
        // fused block trace from fp32 accumulators: g[r,:] . W^a[:, r&127]
        int k = gw & 127, bb = gw >> 7;
        float4 wt = ((const float4*)(g_PT + a * CC + k * CH))[lane];
        float part = ax * wt.x + ay * wt.y + az * wt.z + aw * wt.w;
        part += __shfl_xor_sync(0xffffffffu, part, 16);
        part += __shfl_xor_sync(0xffffffffu, part, 8);
        part += __shfl_xor_sync(0xffffffffu, part, 4);
        part += __shfl_xor_sync(0xffffffffu, part, 2);
        part += __shfl_xor_sync(0xffffffffu, part, 1);
        if (lane == 0) {
            atomicAdd(&g_ptr[(a - 1) * BATN + bb], part);
            if (cpath) {
                g_c[ca][gw] = cacc;
                atomicAdd(&g_q[(a - 1) * BATN + bb], cacc * g_Bv[a * CH + k]);
            }
        }
    } else {
        int w2 = gw - NPV;                            // np graph, 128 dst rows
        const uint2* gin = (const uint2*)&g_hn[pa][0];
        const float* cin = g_cn[pa];
        int s0 = g_rs_n[w2], s1 = g_rs_n[w2 + 1];
        float ax = 0.f, ay = 0.f, az = 0.f, aw = 0.f, cacc = 0.f;
        int e = s0;
        for (; e + 4 <= s1; e += 4) {
            int2 c0 = g_colw_n[e];
            int2 c1 = g_colw_n[e + 1];
            int2 c2 = g_colw_n[e + 2];
            int2 c3 = g_colw_n[e + 3];
            uint2 v0 = gin[c0.x * 32 + lane];
            uint2 v1 = gin[c1.x * 32 + lane];
            uint2 v2 = gin[c2.x * 32 + lane];
            uint2 v3 = gin[c3.x * 32 + lane];
            float w0 = __int_as_float(c0.y), w1 = __int_as_float(c1.y);
            float w2f = __int_as_float(c2.y), w3 = __int_as_float(c3.y);
            FMA8(v0, w0) FMA8(v1, w1) FMA8(v2, w2f) FMA8(v3, w3)
            if (cpath && lane == 0)
                cacc += w0 * cin[c0.x] + w1 * cin[c1.x]
                      + w2f * cin[c2.x] + w3 * cin[c3.x];
        }
        for (; e < s1; e++) {
            int2 c0 = g_colw_n[e];
            uint2 v0 = gin[c0.x * 32 + lane];
            float w0 = __int_as_float(c0.y);
            FMA8(v0, w0)
            if (cpath && lane == 0) cacc += w0 * cin[c0.x];
        }
        if (!last) {
            __half2 o0 = __floats2half2_rn(ax, ay);
            __half2 o1 = __floats2half2_rn(az, aw);
            uint2 st;
            *reinterpret_cast<__half2*>(&st.x) = o0;
            *reinterpret_cast<__half2*>(&st.y) = o1;
            reinterpret_cast<uint2*>(&g_hn[ca][0])[w2 * 32 + lane] = st;
        }
        float4 wt = ((const float4*)(g_PT + a * CC + w2 * CH))[lane];
        float part = ax * wt.x + ay * wt.y + az * wt.z + aw * wt.w;
        part += __shfl_xor_sync(0xffffffffu, part, 16);
        part += __shfl_xor_sync(0xffffffffu, part, 8);
        part += __shfl_xor_sync(0xffffffffu, part, 4);
        part += __shfl_xor_sync(0xffffffffu, part, 2);
        part += __shfl_xor_sync(0xffffffffu, part, 1);
        if (lane == 0) {
            atomicAdd(&g_ntr[a - 1], part);
            if (cpath) {
                g_cn[ca][w2] = cacc;
                atomicAdd(&g_qn[a - 1], cacc * g_Bv[a * CH + w2]);
            }
        }
    }
}

// ---------------- epilogue: bias corr, standardize, MLP, sigmoid, reset -----
__device__ __forceinline__ float blk_sum(float v, float* sm) {
    int t = threadIdx.x, lane = t & 31, w = t >> 5;
    v += __shfl_xor_sync(0xffffffffu, v, 16);
    v += __shfl_xor_sync(0xffffffffu, v, 8);
    v += __shfl_xor_sync(0xffffffffu, v, 4);
    v += __shfl_xor_sync(0xffffffffu, v, 2);
    v += __shfl_xor_sync(0xffffffffu, v, 1);
    if (lane == 0) sm[w] = v;
    __syncthreads();
    if (w == 0) {
        float r = (lane < 8) ? sm[lane] : 0.0f;
        r += __shfl_xor_sync(0xffffffffu, r, 4);
        r += __shfl_xor_sync(0xffffffffu, r, 2);
        r += __shfl_xor_sync(0xffffffffu, r, 1);
        if (lane == 0) sm[8] = r;
    }
    __syncthreads();
    float out = sm[8];
    __syncthreads();
    return out;
}

__global__ void k_epi(const float* __restrict__ y,  const float* __restrict__ bg,
                      const float* __restrict__ W1, const float* __restrict__ b1,
                      const float* __restrict__ W2, const float* __restrict__ b2,
                      float* __restrict__ out) {
    __shared__ float sm[9];
    int b = threadIdx.x;
    float sumb = 0.f;
    for (int k = 0; k < CH; k++) sumb += bg[k];
    float ysc = (y[b] - 0.5f) * 2.0f;

    float v[WALKN];
    float cp = 0.f, cn = 0.f;
    for (int s = 0; s < WALKN; s++) {
        float qp = (s == 0) ? sumb : g_q[(s - 1) * BATN + b];
        float qn = (s == 0) ? sumb : g_qn[s - 1];
        cp += qp; cn += qn;
        float pv = g_ptr[s * BATN + b] + cp;
        float nv = g_ntr[s] + cn;
        v[s] = (pv - nv) * ysc;
    }
    for (int s = 0; s < WALKN; s++) {
        float mu = blk_sum(v[s], sm) * (1.0f / BATN);
        float d = v[s] - mu;
        float var = blk_sum(d * d, sm) * (1.0f / (BATN - 1));
        v[s] = d / sqrtf(var);
    }
    float o2 = b2[0];
    for (int j = 0; j < 15; j++) {
        float h = b1[j];
        for (int s = 0; s < WALKN; s++) h = fmaf(v[s], W1[s * 15 + j], h);
        h = fmaxf(h, 0.0f);
        o2 = fmaf(h, W2[j], o2);
    }
    out[b] = 1.0f / (1.0f + expf(-o2));

    // restore load-time state for the next identical replay
    __syncthreads();
    for (int s = 0; s < WALKN; s++) { g_ptr[s * BATN + b] = 0.0f; g_q[s * BATN + b] = 0.0f; }
    if (b < WALKN) { g_ntr[b] = 0.0f; g_qn[b] = 0.0f; }
    if (b < 32)    g_post[b] = 0;
}

// ---------------- launch ----------------
extern "C" void kernel_launch(void* const* d_in, const int* in_sizes, int n_in,
                              void* d_out, int out_size) {
    const float* x_p  = (const float*)d_in[0];
    const float* x_np = (const float*)d_in[1];
    const float* y    = (const float*)d_in[2];
    const void*  eip  = d_in[3];
    const void*  ein  = d_in[4];
    const float* W    = (const float*)d_in[5];
    const float* bg   = (const float*)d_in[6];
    const float* W1   = (const float*)d_in[7];
    const float* b1   = (const float*)d_in[8];
    const float* W2   = (const float*)d_in[9];
    const float* b2   = (const float*)d_in[10];
    float* out = (float*)d_out;

    k_deg<<<4112, 256>>>(eip, ein, x_p, x_np);
    k_scanfuse<<<50, 1024>>>(W, bg);
    k_fill<<<2185, 256>>>(eip, ein);
    for (int a = 1; a <= WALKN; a++)
        k_agg<<<(NPV + NNV) / 8, 256>>>(a, a == WALKN);
    k_epi<<<1, BATN>>>(y, bg, W1, b1, W2, b2, out);
    (void)in_sizes; (void)n_in; (void)out_size;
}